// round 10
// baseline (speedup 1.0000x reference)
#include <cuda_runtime.h>
#include <cuda_bf16.h>
#include <cstdint>

// ---------------------------------------------------------------------------
// Tree NN as 7 GEMMs fused into ONE persistent kernel (grid=148, 1 CTA/SM):
//   X_{l+1}[M,128] = tanh(X_l.view(M,256) @ W^T + b), 7 levels + classifier.
// concat(left,right) == reinterpret of row-major [2M,128] as [M,256].
// mma.sync bf16 3-term split: D = Ah*Bh + Ah*Bl + Al*Bh (fp32 accum).
// W resident in smem per CTA for the WHOLE run. A K-chunks (64 cols) double
// buffered via cp.async. Grid-wide software barrier between levels (all CTAs
// co-resident). Classifier fused after the last barrier (__ldcg reads).
// (tcgen05 unavailable: harness compiles for plain sm_103.)
// ---------------------------------------------------------------------------

#define STRIDE 72                     // smem row stride in bf16 (64 + 8 pad)
#define PLANE_B (128 * STRIDE * 2)    // 18432 B per 128x64 bf16 plane
#define SM_A    1024                  // 2 bufs x 2 planes
#define SM_W    (SM_A + 4 * PLANE_B)  // 4 chunks x 2 planes
#define SMEM_TOTAL (SM_W + 8 * PLANE_B)   // 222208 B
#define NCTA 148

__device__ __nv_bfloat16 gH0[262144u * 128u];   // 64 MiB  L1,3,5,7 out (hi)
__device__ __nv_bfloat16 gL0[262144u * 128u];   // 64 MiB  (lo)
__device__ __nv_bfloat16 gH1[131072u * 128u];   // 32 MiB  L2,4,6 out (hi)
__device__ __nv_bfloat16 gL1[131072u * 128u];   // 32 MiB  (lo)
__device__ __nv_bfloat16 gWh[128 * 256];
__device__ __nv_bfloat16 gWl[128 * 256];
__device__ int g_tok64;
__device__ volatile unsigned gBarCnt;
__device__ volatile unsigned gBarGen;

__global__ void detect_tok_kernel(const unsigned int* __restrict__ t) {
    if (threadIdx.x == 0) {
        int all_zero = 1;
        for (int i = 1; i < 256; i += 2) all_zero &= (t[i] == 0u);
        g_tok64 = all_zero;
    }
}
__global__ void wsplit_kernel(const float* __restrict__ Wt) {
    int i = blockIdx.x * 256 + threadIdx.x;
    if (i < 128 * 256) {
        float v = Wt[i];
        __nv_bfloat16 h = __float2bfloat16(v);
        gWh[i] = h;
        gWl[i] = __float2bfloat16(v - __bfloat162float(h));
    }
}

__device__ __forceinline__ void grid_barrier() {
    __syncthreads();
    if (threadIdx.x == 0) {
        unsigned gen = gBarGen;
        __threadfence();
        if (atomicAdd((unsigned*)&gBarCnt, 1u) == NCTA - 1) {
            gBarCnt = 0;
            __threadfence();
            gBarGen = gen + 1;
        } else {
            while (gBarGen == gen) { }
        }
        __threadfence();
    }
    __syncthreads();
}

__device__ __forceinline__ float fast_tanh(float x) {
    float e = __expf(2.0f * x);
    return 1.0f - __fdividef(2.0f, e + 1.0f);
}
__device__ __forceinline__ void splitpair(float x0, float x1,
                                          uint32_t& h, uint32_t& l) {
    __nv_bfloat16 h0 = __float2bfloat16(x0), h1 = __float2bfloat16(x1);
    __nv_bfloat16 l0 = __float2bfloat16(x0 - __bfloat162float(h0));
    __nv_bfloat16 l1 = __float2bfloat16(x1 - __bfloat162float(h1));
    h = (uint32_t)__bfloat16_as_ushort(h0) | ((uint32_t)__bfloat16_as_ushort(h1) << 16);
    l = (uint32_t)__bfloat16_as_ushort(l0) | ((uint32_t)__bfloat16_as_ushort(l1) << 16);
}
__device__ __forceinline__ void mma_bf16(float* d, const uint32_t* a,
                                         const uint32_t* b) {
    asm volatile(
        "mma.sync.aligned.m16n8k16.row.col.f32.bf16.bf16.f32 "
        "{%0,%1,%2,%3}, {%4,%5,%6,%7}, {%8,%9}, {%0,%1,%2,%3};\n"
        : "+f"(d[0]), "+f"(d[1]), "+f"(d[2]), "+f"(d[3])
        : "r"(a[0]), "r"(a[1]), "r"(a[2]), "r"(a[3]), "r"(b[0]), "r"(b[1]));
}
__device__ __forceinline__ void ldsm4(uint32_t* r, uint32_t saddr) {
    asm volatile(
        "ldmatrix.sync.aligned.m8n8.x4.shared.b16 {%0,%1,%2,%3}, [%4];\n"
        : "=r"(r[0]), "=r"(r[1]), "=r"(r[2]), "=r"(r[3]) : "r"(saddr));
}
__device__ __forceinline__ void cpa16(uint32_t dst, const void* src) {
    asm volatile("cp.async.cg.shared.global [%0], [%1], 16;" :: "r"(dst), "l"(src));
}
__device__ __forceinline__ void cpa_commit() { asm volatile("cp.async.commit_group;"); }
__device__ __forceinline__ void cpa_wait1() { asm volatile("cp.async.wait_group 1;"); }
__device__ __forceinline__ void cpa_wait0() { asm volatile("cp.async.wait_group 0;"); }

// ---------------------------------------------------------------------------
__global__ __launch_bounds__(256, 1) void tree_fused(
    const void* __restrict__ tokens_raw,
    const float* __restrict__ emb,
    const float* __restrict__ bias,
    const float* __restrict__ Wc,
    const float* __restrict__ bc,
    float* __restrict__ out)
{
    extern __shared__ __align__(1024) unsigned char smem[];
    const uint32_t sb = (uint32_t)__cvta_generic_to_shared(smem);
    const int tid  = threadIdx.x;
    const int lane = tid & 31;
    const int w    = tid >> 5;
    const int tok64 = g_tok64;

    // ---- stage bias + resident W (once for the whole run) ----
    if (tid < 128) ((float*)smem)[tid] = bias[tid];
    for (int i = tid; i < 4096; i += 256) {
        int c = i >> 10, rem = i & 1023;
        int row = rem >> 3, s = rem & 7;
        int src = row * 256 + c * 64 + s * 8;
        uint32_t so = (uint32_t)(row * STRIDE + s * 8) * 2;
        cpa16(sb + SM_W + (c * 2) * PLANE_B + so, gWh + src);
        cpa16(sb + SM_W + (c * 2 + 1) * PLANE_B + so, gWl + src);
    }
    cpa_commit();
    cpa_wait0();                                   // W + bias resident

    // warp geometry: 4 warps M x 2 warps N, warp tile 32x64
    const int wm = (w & 3) * 32;
    const int wn = (w >> 2) * 64;
    const int la_row = lane & 15;
    const int la_col = (lane >> 4) << 3;
    const int lb_n   = ((lane >> 4) << 3) + (lane & 7);
    const int lb_kh  = ((lane >> 3) & 1) << 3;
    const int gr = tid >> 1, gh = tid & 1;         // gather row/half

    float acc[2][8][4];

    for (int l = 0; l < 7; l++) {
        const int tiles = 2048 >> l;
        const int first = (l == 0);
        const int outP0 = !(l & 1);                // L1,3,5,7 -> plane0
        const __nv_bfloat16* AinH = outP0 ? gH1 : gH0;
        const __nv_bfloat16* AinL = outP0 ? gL1 : gL0;
        __nv_bfloat16* AoutH = outP0 ? gH0 : gH1;
        __nv_bfloat16* AoutL = outP0 ? gL0 : gL1;

        int nT = 0;
        for (int t = blockIdx.x; t < tiles; t += NCTA) nT++;
        const int J = nT * 4;

        if (J > 0) {
            float4 R[8];
            int2 RTcur = make_int2(0, 0), RTnext = make_int2(0, 0);

            auto tokLd = [&](int t) -> int2 {
                long long tileIdx = blockIdx.x + (long long)t * NCTA;
                if (tileIdx >= tiles) return make_int2(0, 0);
                long long bi = tileIdx * 256 + 2 * gr;
                int a, b;
                if (tok64) {
                    a = (int)((const long long*)tokens_raw)[bi];
                    b = (int)((const long long*)tokens_raw)[bi + 1];
                } else {
                    int2 v = ((const int2*)tokens_raw)[bi >> 1];
                    a = v.x; b = v.y;
                }
                if ((unsigned)a >= 100000u) a = 0;
                if ((unsigned)b >= 100000u) b = 0;
                return make_int2(a, b);
            };
            auto gatherLd = [&](int c, int tok) {
                const float4* src = (const float4*)emb + (size_t)tok * 32
                                    + (c & 1) * 16 + gh * 8;
#pragma unroll
                for (int i = 0; i < 8; i++) R[i] = __ldg(src + i);
            };
            auto gatherSt = [&](int j) {
                __nv_bfloat16* Ah = (__nv_bfloat16*)(smem + SM_A + ((j & 1) * 2) * PLANE_B);
                __nv_bfloat16* Al = Ah + 128 * STRIDE;
#pragma unroll
                for (int i = 0; i < 8; i++) {
                    int col = gh * 32 + i * 4;
                    uint32_t h0, l0, h1, l1;
                    splitpair(R[i].x, R[i].y, h0, l0);
                    splitpair(R[i].z, R[i].w, h1, l1);
                    *(uint2*)(Ah + gr * STRIDE + col) = make_uint2(h0, h1);
                    *(uint2*)(Al + gr * STRIDE + col) = make_uint2(l0, l1);
                }
            };
            auto stageA_cp = [&](int j) {
                int tl = j >> 2, c = j & 3;
                int m0 = (blockIdx.x + tl * NCTA) * 128;
                uint32_t dH = sb + SM_A + ((j & 1) * 2) * PLANE_B;
                uint32_t dL = dH + PLANE_B;
#pragma unroll
                for (int i = 0; i < 4; i++) {
                    int idx = i * 256 + tid;
                    int row = idx >> 3, s = idx & 7;
                    size_t src = (size_t)(m0 + row) * 256 + c * 64 + s * 8;
                    uint32_t so = (uint32_t)(row * STRIDE + s * 8) * 2;
                    cpa16(dH + so, AinH + src);
                    cpa16(dL + so, AinL + src);
                }
            };

            if (first) {
                RTcur = tokLd(0);
                RTnext = tokLd(1);
                gatherLd(0, RTcur.x); gatherSt(0);
                gatherLd(1, RTcur.x); gatherSt(1);
                gatherLd(2, RTcur.y);
            } else {
                stageA_cp(0); cpa_commit();
                stageA_cp(1); cpa_commit();
            }

#pragma unroll 1
            for (int mt = 0; mt < 2; mt++)
                for (int nt = 0; nt < 8; nt++)
                    for (int q = 0; q < 4; q++) acc[mt][nt][q] = 0.0f;

            for (int j = 0; j < J; j++) {
                const int c = j & 3;
                if (!first) { if (j + 1 < J) cpa_wait1(); else cpa_wait0(); }
                __syncthreads();                   // chunk j visible

                {   // ---- MMA over chunk j (K=64 -> 4 x k16) ----
                    const uint32_t aH = sb + SM_A + ((j & 1) * 2) * PLANE_B;
                    const uint32_t aL = aH + PLANE_B;
                    const uint32_t bH = sb + SM_W + (c * 2) * PLANE_B;
                    const uint32_t bL = bH + PLANE_B;
#pragma unroll
                    for (int ks = 0; ks < 4; ks++) {
                        uint32_t ah[2][4], al[2][4], bh[4][4], bl[4][4];
#pragma unroll
                        for (int mt = 0; mt < 2; mt++) {
                            uint32_t ro = (uint32_t)((wm + mt * 16 + la_row) * STRIDE
                                                     + ks * 16 + la_col) * 2;
                            ldsm4(ah[mt], aH + ro);
                            ldsm4(al[mt], aL + ro);
                        }
#pragma unroll
                        for (int pr = 0; pr < 4; pr++) {
                            uint32_t ro = (uint32_t)((wn + pr * 16 + lb_n) * STRIDE
                                                     + ks * 16 + lb_kh) * 2;
                            ldsm4(bh[pr], bH + ro);
                            ldsm4(bl[pr], bL + ro);
                        }
#pragma unroll
                        for (int mt = 0; mt < 2; mt++)
#pragma unroll
                            for (int nt = 0; nt < 8; nt++) {
                                const uint32_t* bhp = &bh[nt >> 1][(nt & 1) * 2];
                                const uint32_t* blp = &bl[nt >> 1][(nt & 1) * 2];
                                mma_bf16(acc[mt][nt], ah[mt], bhp);
                                mma_bf16(acc[mt][nt], ah[mt], blp);
                                mma_bf16(acc[mt][nt], al[mt], bhp);
                            }
                    }
                }
                __syncthreads();                   // buf j free

                // ---- stage chunk j+2 ----
                if (first) {
                    if (j + 2 < J) gatherSt(j + 2);
                    int jj = j + 3;
                    if (jj < J) {
                        if ((jj & 3) == 0) { RTcur = RTnext; RTnext = tokLd((jj >> 2) + 1); }
                        gatherLd(jj & 3, ((jj & 3) >> 1) ? RTcur.y : RTcur.x);
                    }
                } else {
                    if (j + 2 < J) stageA_cp(j + 2);
                    cpa_commit();                  // keeps group counts aligned
                }

                // ---- tile epilogue ----
                if (c == 3) {
                    const int tl = j >> 2;
                    const int m0 = (blockIdx.x + tl * NCTA) * 128;
                    const float* sB = (const float*)smem;
                    const int g = lane >> 2, t2 = lane & 3;
#pragma unroll
                    for (int mt = 0; mt < 2; mt++)
#pragma unroll
                        for (int nt = 0; nt < 8; nt++) {
                            int col = wn + nt * 8 + 2 * t2;
                            float b0 = sB[col], b1 = sB[col + 1];
#pragma unroll
                            for (int h = 0; h < 2; h++) {
                                size_t row = (size_t)m0 + wm + mt * 16 + g + h * 8;
                                float v0 = fast_tanh(acc[mt][nt][h * 2 + 0] + b0);
                                float v1 = fast_tanh(acc[mt][nt][h * 2 + 1] + b1);
                                uint32_t hp, lp;
                                splitpair(v0, v1, hp, lp);
                                *(uint32_t*)(AoutH + row * 128 + col) = hp;
                                *(uint32_t*)(AoutL + row * 128 + col) = lp;
                            }
                        }
#pragma unroll
                    for (int mt = 0; mt < 2; mt++)
#pragma unroll
                        for (int nt = 0; nt < 8; nt++)
#pragma unroll
                            for (int q = 0; q < 4; q++) acc[mt][nt][q] = 0.0f;
                }
            }
        }
        grid_barrier();                            // level l complete everywhere
    }

    // ---- fused classifier: out[b,j] = root[b] . Wc[j] + bc[j] ----
    for (int r = blockIdx.x * 8 + w; r < 4096; r += NCTA * 8) {
        size_t base = (size_t)r * 128 + lane * 4;
        uint2 ph = __ldcg((const uint2*)(gH0 + base));
        uint2 pl = __ldcg((const uint2*)(gL0 + base));
        float x[4];
#pragma unroll
        for (int q = 0; q < 2; q++) {
            uint32_t hw = ((uint32_t*)&ph)[q], lw = ((uint32_t*)&pl)[q];
            x[2*q]   = __bfloat162float(__ushort_as_bfloat16((unsigned short)(hw & 0xffffu)))
                     + __bfloat162float(__ushort_as_bfloat16((unsigned short)(lw & 0xffffu)));
            x[2*q+1] = __bfloat162float(__ushort_as_bfloat16((unsigned short)(hw >> 16)))
                     + __bfloat162float(__ushort_as_bfloat16((unsigned short)(lw >> 16)));
        }
        float s0 = 0.f, s1 = 0.f, s2 = 0.f;
#pragma unroll
        for (int q = 0; q < 4; q++) {
            int e = lane * 4 + q;
            s0 += x[q] * __ldg(Wc + e);
            s1 += x[q] * __ldg(Wc + 128 + e);
            s2 += x[q] * __ldg(Wc + 256 + e);
        }
#pragma unroll
        for (int o = 16; o; o >>= 1) {
            s0 += __shfl_xor_sync(0xffffffffu, s0, o);
            s1 += __shfl_xor_sync(0xffffffffu, s1, o);
            s2 += __shfl_xor_sync(0xffffffffu, s2, o);
        }
        if (lane == 0) {
            out[r * 3 + 0] = s0 + __ldg(bc + 0);
            out[r * 3 + 1] = s1 + __ldg(bc + 1);
            out[r * 3 + 2] = s2 + __ldg(bc + 2);
        }
    }
}

extern "C" void kernel_launch(void* const* d_in, const int* in_sizes, int n_in,
                              void* d_out, int out_size)
{
    const void* tokens = d_in[0];
    const float* emb = (const float*)d_in[1];
    const float* Wt  = (const float*)d_in[2];
    const float* bt  = (const float*)d_in[3];
    const float* Wc  = (const float*)d_in[4];
    const float* bc  = (const float*)d_in[5];
    float* out = (float*)d_out;

    cudaFuncSetAttribute(tree_fused,
                         cudaFuncAttributeMaxDynamicSharedMemorySize, SMEM_TOTAL);

    detect_tok_kernel<<<1, 32>>>((const unsigned int*)tokens);
    wsplit_kernel<<<128, 256>>>(Wt);
    tree_fused<<<NCTA, 256, SMEM_TOTAL>>>(tokens, emb, bt, Wc, bc, out);
}

// round 11
// speedup vs baseline: 3.4695x; 3.4695x over previous
#include <cuda_runtime.h>
#include <cuda_fp16.h>
#include <cstdint>

// ---------------------------------------------------------------------------
// Tree NN as 7 GEMMs: X_{l+1}[M,128] = tanh(X_l.view(M,256) @ W^T + b).
// concat(left,right) == reinterpret of row-major [2M,128] as [M,256].
// Precision: activations single fp16 (u=2^-11), W split fp16 hi/lo:
//   D = A*Wh + A*Wl  (fp32 accum) -> only error is A's fp16 rounding ~3e-4.
// Per-level kernels (R6 architecture: proven fastest), M_TILE=64, K chunks
// of 64 double-buffered via cp.async (W with .ca for L1 reuse), ldmatrix
// fragments, 2 CTAs/SM (91KB smem).
// ---------------------------------------------------------------------------

#define STRIDE 72                    // smem row stride in halves (64 + 8 pad)
#define A_PL (64 * STRIDE)           // 4608 halves  (A chunk plane)
#define W_PL (128 * STRIDE)          // 9216 halves  (W chunk plane)
#define BUF_ELE (A_PL + 2 * W_PL)    // 23040 halves per pipeline buffer
#define SMEM_BYTES (2 * BUF_ELE * 2 + 1024)   // 93184 B

__device__ __half gA0[262144u * 128u];   // 64 MiB: L1,3,5,7 outputs
__device__ __half gA1[131072u * 128u];   // 32 MiB: L2,4,6 outputs
__device__ __half gWh[128 * 256];
__device__ __half gWl[128 * 256];
__device__ int g_tok64;

__global__ void detect_tok_kernel(const unsigned int* __restrict__ t) {
    if (threadIdx.x == 0) {
        int all_zero = 1;
        for (int i = 1; i < 256; i += 2) all_zero &= (t[i] == 0u);
        g_tok64 = all_zero;
    }
}
// split W (f32 [128][256]) into fp16 hi/lo planes
__global__ void wsplit_kernel(const float* __restrict__ Wt) {
    int i = blockIdx.x * 256 + threadIdx.x;
    if (i < 128 * 256) {
        float v = Wt[i];
        __half h = __float2half_rn(v);
        gWh[i] = h;
        gWl[i] = __float2half_rn(v - __half2float(h));
    }
}

__device__ __forceinline__ float fast_tanh(float x) {
    float e = __expf(2.0f * x);
    return 1.0f - __fdividef(2.0f, e + 1.0f);
}
__device__ __forceinline__ uint32_t packh2(float x0, float x1) {
    __half h0 = __float2half_rn(x0), h1 = __float2half_rn(x1);
    return (uint32_t)__half_as_ushort(h0) | ((uint32_t)__half_as_ushort(h1) << 16);
}
__device__ __forceinline__ void mma_fp16(float* d, const uint32_t* a,
                                         const uint32_t* b) {
    asm volatile(
        "mma.sync.aligned.m16n8k16.row.col.f32.f16.f16.f32 "
        "{%0,%1,%2,%3}, {%4,%5,%6,%7}, {%8,%9}, {%0,%1,%2,%3};\n"
        : "+f"(d[0]), "+f"(d[1]), "+f"(d[2]), "+f"(d[3])
        : "r"(a[0]), "r"(a[1]), "r"(a[2]), "r"(a[3]), "r"(b[0]), "r"(b[1]));
}
__device__ __forceinline__ void ldsm4(uint32_t* r, uint32_t saddr) {
    asm volatile(
        "ldmatrix.sync.aligned.m8n8.x4.shared.b16 {%0,%1,%2,%3}, [%4];\n"
        : "=r"(r[0]), "=r"(r[1]), "=r"(r[2]), "=r"(r[3]) : "r"(saddr));
}
__device__ __forceinline__ void cpaA16(uint32_t dst, const void* src) {
    asm volatile("cp.async.cg.shared.global [%0], [%1], 16;" :: "r"(dst), "l"(src));
}
__device__ __forceinline__ void cpaW16(uint32_t dst, const void* src) {
    asm volatile("cp.async.ca.shared.global [%0], [%1], 16;" :: "r"(dst), "l"(src));
}
__device__ __forceinline__ void cpa_commit() { asm volatile("cp.async.commit_group;"); }
__device__ __forceinline__ void cpa_wait1() { asm volatile("cp.async.wait_group 1;"); }
__device__ __forceinline__ void cpa_wait0() { asm volatile("cp.async.wait_group 0;"); }

// One level. Grid.x = M/64, 256 threads, 2 CTAs/SM.
__global__ __launch_bounds__(256, 2) void tree_level_kernel(
    const void* __restrict__ tokens_raw,
    const float* __restrict__ emb,
    const float* __restrict__ bias,
    int first, int flip)
{
    extern __shared__ __align__(16) __half smem[];
    int* sTok = (int*)(smem + 2 * BUF_ELE);
    const uint32_t sb = (uint32_t)__cvta_generic_to_shared(smem);

    const __half* Ain = flip ? gA1 : gA0;
    __half* Aout      = flip ? gA0 : gA1;

    const int tid = threadIdx.x;
    const int m0 = blockIdx.x * 64;

    if (first) {
        if (tid < 128) {
            long long ti = (long long)m0 * 2 + tid;
            int tok = g_tok64 ? (int)((const long long*)tokens_raw)[ti]
                              : ((const int*)tokens_raw)[ti];
            if ((unsigned)tok >= 100000u) tok = 0;
            sTok[tid] = tok;
        }
        __syncthreads();
    }

    const int grow  = tid >> 2;        // gather row 0..63
    const int gslot = tid & 3;         // 4 float4 slots per thread
    float4 R[4];

    auto stageW = [&](int c, int buf) {
        uint32_t b = sb + (buf * BUF_ELE) * 2;
#pragma unroll
        for (int i = 0; i < 4; i++) {
            int idx = i * 256 + tid;          // 1024 16B chunks per plane
            int row = idx >> 3, s = idx & 7;
            int src = row * 256 + c * 64 + s * 8;
            uint32_t so = (uint32_t)(row * STRIDE + s * 8) * 2;
            cpaW16(b + (A_PL * 2) + so, gWh + src);
            cpaW16(b + ((A_PL + W_PL) * 2) + so, gWl + src);
        }
    };
    auto stageA = [&](int c, int buf) {
        uint32_t b = sb + (buf * BUF_ELE) * 2;
#pragma unroll
        for (int i = 0; i < 2; i++) {
            int idx = i * 256 + tid;          // 512 16B chunks
            int row = idx >> 3, s = idx & 7;
            size_t src = (size_t)(m0 + row) * 256 + c * 64 + s * 8;
            uint32_t so = (uint32_t)(row * STRIDE + s * 8) * 2;
            cpaA16(b + so, Ain + src);
        }
    };
    auto gatherLd = [&](int c) {
        int tok = sTok[grow * 2 + (c >> 1)];
        const float4* src = (const float4*)emb + (size_t)tok * 32 + (c & 1) * 16;
#pragma unroll
        for (int j = 0; j < 4; j++) R[j] = __ldg(src + gslot + j * 4);
    };
    auto gatherSt = [&](int buf) {
        __half* Ah = smem + buf * BUF_ELE;
#pragma unroll
        for (int j = 0; j < 4; j++) {
            int col = (gslot + j * 4) * 4;
            uint2 pk;
            pk.x = packh2(R[j].x, R[j].y);
            pk.y = packh2(R[j].z, R[j].w);
            *(uint2*)(Ah + grow * STRIDE + col) = pk;
        }
    };

    // ---- pipeline prologue: chunks 0,1 ----
    if (first) {
        gatherLd(0); stageW(0, 0); cpa_commit(); gatherSt(0);
        gatherLd(1); stageW(1, 1); cpa_commit(); gatherSt(1);
        gatherLd(2);
    } else {
        stageA(0, 0); stageW(0, 0); cpa_commit();
        stageA(1, 1); stageW(1, 1); cpa_commit();
    }

    // ---- warp/fragment geometry: 2 warps M x 4 warps N, warp tile 32x32 ----
    const int lane = tid & 31;
    const int w    = tid >> 5;
    const int wm   = (w >> 2) * 32;
    const int wn   = (w & 3) * 32;
    const int la_row = lane & 15;
    const int la_col = (lane >> 4) << 3;
    const int lb_n   = ((lane >> 4) << 3) + (lane & 7);
    const int lb_kh  = ((lane >> 3) & 1) << 3;

    float acc[2][4][4] = {};

    for (int c = 0; c < 4; c++) {
        if (c < 3) cpa_wait1(); else cpa_wait0();
        __syncthreads();
        const int buf = c & 1;
        const uint32_t bB = sb + (buf * BUF_ELE) * 2;
        const uint32_t aS = bB;
        const uint32_t bHs = bB + A_PL * 2;
        const uint32_t bLs = bB + (A_PL + W_PL) * 2;
#pragma unroll
        for (int ks = 0; ks < 4; ks++) {
            uint32_t ah[2][4], bh[2][4], bl[2][4];
#pragma unroll
            for (int mt = 0; mt < 2; mt++) {
                uint32_t ro = (uint32_t)((wm + mt * 16 + la_row) * STRIDE
                                         + ks * 16 + la_col) * 2;
                ldsm4(ah[mt], aS + ro);
            }
#pragma unroll
            for (int pr = 0; pr < 2; pr++) {
                uint32_t ro = (uint32_t)((wn + pr * 16 + lb_n) * STRIDE
                                         + ks * 16 + lb_kh) * 2;
                ldsm4(bh[pr], bHs + ro);
                ldsm4(bl[pr], bLs + ro);
            }
#pragma unroll
            for (int mt = 0; mt < 2; mt++)
#pragma unroll
                for (int nt = 0; nt < 4; nt++) {
                    const uint32_t* bhp = &bh[nt >> 1][(nt & 1) * 2];
                    const uint32_t* blp = &bl[nt >> 1][(nt & 1) * 2];
                    mma_fp16(acc[mt][nt], ah[mt], bhp);
                    mma_fp16(acc[mt][nt], ah[mt], blp);
                }
        }
        __syncthreads();
        if (c < 2) {
            if (first) { stageW(c + 2, buf); cpa_commit(); gatherSt(buf);
                         if (c == 0) gatherLd(3); }
            else       { stageA(c + 2, buf); stageW(c + 2, buf); cpa_commit(); }
        } else {
            cpa_commit();   // empty group keeps wait count consistent
        }
    }

    // ---- epilogue: bias + tanh + fp16 store ----
    const int g  = lane >> 2;
    const int t2 = lane & 3;
#pragma unroll
    for (int mt = 0; mt < 2; mt++)
#pragma unroll
        for (int nt = 0; nt < 4; nt++) {
            int col = wn + nt * 8 + 2 * t2;
            float b0 = __ldg(bias + col);
            float b1 = __ldg(bias + col + 1);
#pragma unroll
            for (int h = 0; h < 2; h++) {
                size_t row = (size_t)m0 + wm + mt * 16 + g + h * 8;
                float v0 = fast_tanh(acc[mt][nt][h * 2 + 0] + b0);
                float v1 = fast_tanh(acc[mt][nt][h * 2 + 1] + b1);
                *(uint32_t*)(Aout + row * 128 + col) = packh2(v0, v1);
            }
        }
}

// classifier: out[b,j] = root[b,:] . W_cls[j,:] + b_cls[j]; one warp per row
__global__ __launch_bounds__(256) void cls_kernel(
    const float* __restrict__ Wc, const float* __restrict__ bc,
    float* __restrict__ out)
{
    int warp = (blockIdx.x * 256 + threadIdx.x) >> 5;
    int lane = threadIdx.x & 31;
    if (warp >= 4096) return;
    size_t base = (size_t)warp * 128;
    float s0 = 0.f, s1 = 0.f, s2 = 0.f;
#pragma unroll
    for (int i = 0; i < 4; i++) {
        int e = lane + i * 32;
        float x = __half2float(gA0[base + e]);
        s0 += x * __ldg(Wc + e);
        s1 += x * __ldg(Wc + 128 + e);
        s2 += x * __ldg(Wc + 256 + e);
    }
#pragma unroll
    for (int o = 16; o; o >>= 1) {
        s0 += __shfl_xor_sync(0xffffffffu, s0, o);
        s1 += __shfl_xor_sync(0xffffffffu, s1, o);
        s2 += __shfl_xor_sync(0xffffffffu, s2, o);
    }
    if (lane == 0) {
        out[warp * 3 + 0] = s0 + __ldg(bc + 0);
        out[warp * 3 + 1] = s1 + __ldg(bc + 1);
        out[warp * 3 + 2] = s2 + __ldg(bc + 2);
    }
}

extern "C" void kernel_launch(void* const* d_in, const int* in_sizes, int n_in,
                              void* d_out, int out_size)
{
    const void* tokens = d_in[0];
    const float* emb = (const float*)d_in[1];
    const float* Wt  = (const float*)d_in[2];
    const float* bt  = (const float*)d_in[3];
    const float* Wc  = (const float*)d_in[4];
    const float* bc  = (const float*)d_in[5];
    float* out = (float*)d_out;

    cudaFuncSetAttribute(tree_level_kernel,
                         cudaFuncAttributeMaxDynamicSharedMemorySize, SMEM_BYTES);

    detect_tok_kernel<<<1, 32>>>((const unsigned int*)tokens);
    wsplit_kernel<<<128, 256>>>(Wt);
    // L1 gather -> gA0 (flip=1); then alternate.  grid = M/64
    tree_level_kernel<<<4096, 256, SMEM_BYTES>>>(tokens, emb, bt, 1, 1);
    tree_level_kernel<<<2048, 256, SMEM_BYTES>>>(tokens, emb, bt, 0, 0);
    tree_level_kernel<<<1024, 256, SMEM_BYTES>>>(tokens, emb, bt, 0, 1);
    tree_level_kernel<<< 512, 256, SMEM_BYTES>>>(tokens, emb, bt, 0, 0);
    tree_level_kernel<<< 256, 256, SMEM_BYTES>>>(tokens, emb, bt, 0, 1);
    tree_level_kernel<<< 128, 256, SMEM_BYTES>>>(tokens, emb, bt, 0, 0);
    tree_level_kernel<<<  64, 256, SMEM_BYTES>>>(tokens, emb, bt, 0, 1);
    cls_kernel<<<512, 256>>>(Wc, bc, out);
}